// round 3
// baseline (speedup 1.0000x reference)
#include <cuda_runtime.h>

#define B_   1024
#define F_   32
#define D_   64
#define P_   496
#define OUT_ 512
#define RED_ 32
#define EMB_ 2048
#define ROWSTRIDE_ 2560
#define EPS_ 1e-6f

__device__ float g_dots[B_ * P_];  // scratch (no cudaMalloc allowed)

// ---------------------------------------------------------------------------
// Kernel 1: SENET branch, fused: squeeze(z) -> a1 -> weights -> scale -> LN
// 4 batch rows per block (W2 reuse: 4x less L2 traffic), 256 threads
// ---------------------------------------------------------------------------
__global__ __launch_bounds__(256) void senet_kernel(
    const float* __restrict__ x, const float* __restrict__ W1,
    const float* __restrict__ b1, const float* __restrict__ W2,
    const float* __restrict__ b2, const float* __restrict__ ln_scale,
    const float* __restrict__ ln_bias, float* __restrict__ out)
{
    __shared__ float sx[4][EMB_];        // 32 KB
    __shared__ float sz[4][128];
    __shared__ float sa1[4][RED_];
    __shared__ float rsum[4][8], rsq[4][8];
    __shared__ float s_mu[4], s_rstd[4];

    int b0 = blockIdx.x * 4, tid = threadIdx.x;

    // load 4 x rows (4 x 2048 floats) as float4
    const float4* xb4 = (const float4*)(x + (size_t)b0 * EMB_);
    #pragma unroll
    for (int r = 0; r < 8; r++)
        ((float4*)sx)[tid + r * 256] = xb4[tid + r * 256];
    __syncthreads();

    // z per row: (F, 2g) = (32, 4): [max g0, max g1, mean g0, mean g1]
    // 512 tasks over 256 threads
    #pragma unroll
    for (int t = 0; t < 2; t++) {
        int task = tid + t * 256;
        int row = task >> 7, sub = task & 127;
        int f = sub >> 2, k = sub & 3;
        int grp = k & 1;
        const float* base = sx[row] + f * 64 + grp * 32;
        if (k < 2) {
            float m = base[0];
            #pragma unroll
            for (int q = 1; q < 32; q++) m = fmaxf(m, base[q]);
            sz[row][sub] = m;
        } else {
            float s = 0.f;
            #pragma unroll
            for (int q = 0; q < 32; q++) s += base[q];
            sz[row][sub] = s * (1.0f / 32.0f);
        }
    }
    __syncthreads();

    // a1 = relu(z @ W1 + b1): 4 rows x 32 outputs = 128 tasks
    if (tid < 128) {
        int row = tid >> 5, o = tid & 31;
        float s = b1[o];
        #pragma unroll 8
        for (int k = 0; k < 128; k++) s += sz[row][k] * W1[k * RED_ + o];
        sa1[row][o] = fmaxf(s, 0.f);
    }
    __syncthreads();

    // weights = a1 @ W2 + b2 ; senet = flat*weights + flat ; accumulate stats
    float v[4][8];
    float lsum[4] = {0.f, 0.f, 0.f, 0.f};
    float lsq[4]  = {0.f, 0.f, 0.f, 0.f};
    #pragma unroll
    for (int r8 = 0; r8 < 8; r8++) {
        int e = tid + r8 * 256;
        float bb = b2[e];
        float w0 = bb, w1 = bb, w2a = bb, w3 = bb;
        #pragma unroll 8
        for (int j = 0; j < RED_; j++) {
            float w2e = W2[j * EMB_ + e];
            w0  = fmaf(sa1[0][j], w2e, w0);
            w1  = fmaf(sa1[1][j], w2e, w1);
            w2a = fmaf(sa1[2][j], w2e, w2a);
            w3  = fmaf(sa1[3][j], w2e, w3);
        }
        float f0 = sx[0][e], f1 = sx[1][e], f2 = sx[2][e], f3 = sx[3][e];
        float s0 = fmaf(f0, w0, f0);
        float s1 = fmaf(f1, w1, f1);
        float s2 = fmaf(f2, w2a, f2);
        float s3 = fmaf(f3, w3, f3);
        v[0][r8] = s0; v[1][r8] = s1; v[2][r8] = s2; v[3][r8] = s3;
        lsum[0] += s0; lsq[0] += s0 * s0;
        lsum[1] += s1; lsq[1] += s1 * s1;
        lsum[2] += s2; lsq[2] += s2 * s2;
        lsum[3] += s3; lsq[3] += s3 * s3;
    }
    // block reduce (4 rows)
    #pragma unroll
    for (int o = 16; o; o >>= 1) {
        #pragma unroll
        for (int r = 0; r < 4; r++) {
            lsum[r] += __shfl_down_sync(0xFFFFFFFFu, lsum[r], o);
            lsq[r]  += __shfl_down_sync(0xFFFFFFFFu, lsq[r], o);
        }
    }
    if ((tid & 31) == 0) {
        int w = tid >> 5;
        #pragma unroll
        for (int r = 0; r < 4; r++) { rsum[r][w] = lsum[r]; rsq[r][w] = lsq[r]; }
    }
    __syncthreads();
    if (tid < 4) {
        float a = 0.f, c = 0.f;
        #pragma unroll
        for (int i = 0; i < 8; i++) { a += rsum[tid][i]; c += rsq[tid][i]; }
        float mu = a * (1.0f / EMB_);
        float var = c * (1.0f / EMB_) - mu * mu;
        s_mu[tid] = mu;
        s_rstd[tid] = rsqrtf(var + EPS_);
    }
    __syncthreads();
    #pragma unroll
    for (int r = 0; r < 4; r++) {
        float mu = s_mu[r], rstd = s_rstd[r];
        float* ob = out + (size_t)(b0 + r) * ROWSTRIDE_;
        #pragma unroll
        for (int r8 = 0; r8 < 8; r8++) {
            int e = tid + r8 * 256;
            ob[e] = fmaf((v[r][r8] - mu) * rstd, ln_scale[e], ln_bias[e]);
        }
    }
}

// ---------------------------------------------------------------------------
// Kernel 2: dots[b,p] = x_i^T Wp[p] x_j + bp[p].x_j
// grid (P, B/128); block 256 threads = 16x16; each thread 8 rows x 4 cols
// FMA-issue bound by design (FFMA fraction ~78% of issue slots; crossbar has
// headroom: ~10 LDS wavefronts vs 32 FFMA per warp per d).
// ---------------------------------------------------------------------------
__global__ __launch_bounds__(256) void bilinear_dots_kernel(
    const float* __restrict__ x, const float* __restrict__ Wp,
    const float* __restrict__ bp)
{
    __shared__ float sW[64 * 64];        // Wp[p], [d][e]   (16 KB)
    __shared__ float sXi[128 * 64];      // 128 batches x 64 d (32 KB)

    int p = blockIdx.x;
    int b0 = blockIdx.y * 128;
    int tid = threadIdx.x;

    // pair (i, j) from p
    int i = 0, rem = p, cnt = F_ - 1;
    while (rem >= cnt) { rem -= cnt; i++; cnt--; }
    int j = i + 1 + rem;

    // load Wp[p]: 4096 floats = 1024 float4
    const float4* Wp4 = (const float4*)(Wp + (size_t)p * 4096);
    #pragma unroll
    for (int r = 0; r < 4; r++)
        ((float4*)sW)[tid + r * 256] = Wp4[tid + r * 256];

    // load Xi tile (128 rows x 64 floats)
    #pragma unroll
    for (int r = 0; r < 8; r++) {
        int idx = tid + r * 256;
        int row = idx >> 4, cg = idx & 15;
        *(float4*)(sXi + row * 64 + cg * 4) =
            *(const float4*)(x + (size_t)(b0 + row) * EMB_ + i * D_ + cg * 4);
    }
    __syncthreads();

    int tx = tid & 15, ty = tid >> 4;
    int colBase = tx * 4;
    int rowBase = ty * 8;

    float acc[8][4];
    #pragma unroll
    for (int r = 0; r < 8; r++)
        #pragma unroll
        for (int c = 0; c < 4; c++) acc[r][c] = 0.f;

    #pragma unroll 4
    for (int d = 0; d < 64; d++) {
        float4 w = *(float4*)&sW[d * 64 + colBase];
        #pragma unroll
        for (int rr = 0; rr < 8; rr++) {
            float xi = sXi[(rowBase + rr) * 64 + d];
            acc[rr][0] = fmaf(xi, w.x, acc[rr][0]);
            acc[rr][1] = fmaf(xi, w.y, acc[rr][1]);
            acc[rr][2] = fmaf(xi, w.z, acc[rr][2]);
            acc[rr][3] = fmaf(xi, w.w, acc[rr][3]);
        }
    }

    float4 bpv = *(const float4*)(bp + (size_t)p * D_ + colBase);
    float part[8];
    #pragma unroll
    for (int rr = 0; rr < 8; rr++) {
        int row = rowBase + rr;
        float4 xj = *(const float4*)(x + (size_t)(b0 + row) * EMB_ + j * D_ + colBase);
        part[rr] = (acc[rr][0] + bpv.x) * xj.x + (acc[rr][1] + bpv.y) * xj.y
                 + (acc[rr][2] + bpv.z) * xj.z + (acc[rr][3] + bpv.w) * xj.w;
    }
    // reduce over the 16 tx lanes (each half-warp is one ty group)
    #pragma unroll
    for (int o = 8; o; o >>= 1) {
        #pragma unroll
        for (int rr = 0; rr < 8; rr++)
            part[rr] += __shfl_down_sync(0xFFFFFFFFu, part[rr], o, 16);
    }
    if (tx == 0) {
        #pragma unroll
        for (int rr = 0; rr < 8; rr++)
            g_dots[(size_t)(b0 + rowBase + rr) * P_ + p] = part[rr];
    }
}

// ---------------------------------------------------------------------------
// Kernel 3: bilinear = dots (1024x496) @ Wo (496x512) + bo -> out[:, 2048:]
// BM=BN=64, BK=16, 256 threads, 4x4 micro-tile
// ---------------------------------------------------------------------------
__global__ __launch_bounds__(256) void bilinear_out_kernel(
    const float* __restrict__ Wo, const float* __restrict__ bo,
    float* __restrict__ out)
{
    __shared__ float sA[16][68];   // [k][m]
    __shared__ float sB[16][64];   // [k][n]

    int m0 = blockIdx.x * 64;
    int n0 = blockIdx.y * 64;
    int tid = threadIdx.x;
    int tx = tid & 15, ty = tid >> 4;

    float acc[4][4];
    #pragma unroll
    for (int r = 0; r < 4; r++)
        #pragma unroll
        for (int c = 0; c < 4; c++) acc[r][c] = 0.f;

    for (int kc = 0; kc < P_; kc += 16) {
        // A tile (dots): thread loads float4 along k, stores transposed
        {
            int row = tid >> 2, kq = tid & 3;
            float4 a = *(const float4*)(&g_dots[(size_t)(m0 + row) * P_ + kc + kq * 4]);
            sA[kq * 4 + 0][row] = a.x;
            sA[kq * 4 + 1][row] = a.y;
            sA[kq * 4 + 2][row] = a.z;
            sA[kq * 4 + 3][row] = a.w;
        }
        // B tile (Wo)
        {
            int kk = tid >> 4, cg = tid & 15;
            float4 bvec = *(const float4*)(Wo + (size_t)(kc + kk) * OUT_ + n0 + cg * 4);
            *(float4*)&sB[kk][cg * 4] = bvec;
        }
        __syncthreads();

        #pragma unroll
        for (int kk = 0; kk < 16; kk++) {
            float a0 = sA[kk][ty * 4 + 0];
            float a1 = sA[kk][ty * 4 + 1];
            float a2 = sA[kk][ty * 4 + 2];
            float a3 = sA[kk][ty * 4 + 3];
            float4 bv = *(float4*)&sB[kk][tx * 4];
            acc[0][0] = fmaf(a0, bv.x, acc[0][0]); acc[0][1] = fmaf(a0, bv.y, acc[0][1]);
            acc[0][2] = fmaf(a0, bv.z, acc[0][2]); acc[0][3] = fmaf(a0, bv.w, acc[0][3]);
            acc[1][0] = fmaf(a1, bv.x, acc[1][0]); acc[1][1] = fmaf(a1, bv.y, acc[1][1]);
            acc[1][2] = fmaf(a1, bv.z, acc[1][2]); acc[1][3] = fmaf(a1, bv.w, acc[1][3]);
            acc[2][0] = fmaf(a2, bv.x, acc[2][0]); acc[2][1] = fmaf(a2, bv.y, acc[2][1]);
            acc[2][2] = fmaf(a2, bv.z, acc[2][2]); acc[2][3] = fmaf(a2, bv.w, acc[2][3]);
            acc[3][0] = fmaf(a3, bv.x, acc[3][0]); acc[3][1] = fmaf(a3, bv.y, acc[3][1]);
            acc[3][2] = fmaf(a3, bv.z, acc[3][2]); acc[3][3] = fmaf(a3, bv.w, acc[3][3]);
        }
        __syncthreads();
    }

    #pragma unroll
    for (int rr = 0; rr < 4; rr++) {
        int row = m0 + ty * 4 + rr;
        float* orow = out + (size_t)row * ROWSTRIDE_ + EMB_ + n0 + tx * 4;
        float4 bov = *(const float4*)(bo + n0 + tx * 4);
        float4 o;
        o.x = acc[rr][0] + bov.x;
        o.y = acc[rr][1] + bov.y;
        o.z = acc[rr][2] + bov.z;
        o.w = acc[rr][3] + bov.w;
        *(float4*)orow = o;
    }
}

// ---------------------------------------------------------------------------
extern "C" void kernel_launch(void* const* d_in, const int* in_sizes, int n_in,
                              void* d_out, int out_size)
{
    const float* x        = (const float*)d_in[0];
    const float* W1       = (const float*)d_in[1];
    const float* b1       = (const float*)d_in[2];
    const float* W2       = (const float*)d_in[3];
    const float* b2       = (const float*)d_in[4];
    const float* ln_scale = (const float*)d_in[5];
    const float* ln_bias  = (const float*)d_in[6];
    const float* Wp       = (const float*)d_in[7];
    const float* bp       = (const float*)d_in[8];
    const float* Wo       = (const float*)d_in[9];
    const float* bo       = (const float*)d_in[10];
    float* out = (float*)d_out;

    bilinear_dots_kernel<<<dim3(P_, B_ / 128), 256>>>(x, Wp, bp);
    senet_kernel<<<B_ / 4, 256>>>(x, W1, b1, W2, b2, ln_scale, ln_bias, out);
    bilinear_out_kernel<<<dim3(B_ / 64, OUT_ / 64), 256>>>(Wo, bo, out);
}

// round 4
// speedup vs baseline: 1.0578x; 1.0578x over previous
#include <cuda_runtime.h>

#define B_   1024
#define F_   32
#define D_   64
#define P_   496
#define OUT_ 512
#define RED_ 32
#define EMB_ 2048
#define ROWSTRIDE_ 2560
#define EPS_ 1e-6f

__device__ float g_dots[B_ * P_];  // scratch (no cudaMalloc allowed)

// ---- packed f32x2 helpers (Blackwell FFMA2: 2 FMAs per instruction) -------
__device__ __forceinline__ unsigned long long pack2(float lo, float hi) {
    unsigned long long r;
    asm("mov.b64 %0, {%1, %2};" : "=l"(r) : "f"(lo), "f"(hi));
    return r;
}
__device__ __forceinline__ void fma2(unsigned long long& d,
                                     unsigned long long a,
                                     unsigned long long b) {
    asm("fma.rn.f32x2 %0, %1, %2, %0;" : "+l"(d) : "l"(a), "l"(b));
}
__device__ __forceinline__ float2 unpack2(unsigned long long v) {
    float2 f;
    asm("mov.b64 {%0, %1}, %2;" : "=f"(f.x), "=f"(f.y) : "l"(v));
    return f;
}

// ---------------------------------------------------------------------------
// Kernel 1: SENET branch, fused: squeeze(z) -> a1 -> weights -> scale -> LN
// 4 batch rows per block (W2 reuse: 4x less L2 traffic), 256 threads
// ---------------------------------------------------------------------------
__global__ __launch_bounds__(256) void senet_kernel(
    const float* __restrict__ x, const float* __restrict__ W1,
    const float* __restrict__ b1, const float* __restrict__ W2,
    const float* __restrict__ b2, const float* __restrict__ ln_scale,
    const float* __restrict__ ln_bias, float* __restrict__ out)
{
    __shared__ float sx[4][EMB_];        // 32 KB
    __shared__ float sz[4][128];
    __shared__ float sa1[4][RED_];
    __shared__ float rsum[4][8], rsq[4][8];
    __shared__ float s_mu[4], s_rstd[4];

    int b0 = blockIdx.x * 4, tid = threadIdx.x;

    // load 4 x rows (4 x 2048 floats) as float4
    const float4* xb4 = (const float4*)(x + (size_t)b0 * EMB_);
    #pragma unroll
    for (int r = 0; r < 8; r++)
        ((float4*)sx)[tid + r * 256] = xb4[tid + r * 256];
    __syncthreads();

    // z per row: (F, 2g) = (32, 4): [max g0, max g1, mean g0, mean g1]
    #pragma unroll
    for (int t = 0; t < 2; t++) {
        int task = tid + t * 256;
        int row = task >> 7, sub = task & 127;
        int f = sub >> 2, k = sub & 3;
        int grp = k & 1;
        const float* base = sx[row] + f * 64 + grp * 32;
        if (k < 2) {
            float m = base[0];
            #pragma unroll
            for (int q = 1; q < 32; q++) m = fmaxf(m, base[q]);
            sz[row][sub] = m;
        } else {
            float s = 0.f;
            #pragma unroll
            for (int q = 0; q < 32; q++) s += base[q];
            sz[row][sub] = s * (1.0f / 32.0f);
        }
    }
    __syncthreads();

    // a1 = relu(z @ W1 + b1): 4 rows x 32 outputs = 128 tasks
    if (tid < 128) {
        int row = tid >> 5, o = tid & 31;
        float s = b1[o];
        #pragma unroll 8
        for (int k = 0; k < 128; k++) s += sz[row][k] * W1[k * RED_ + o];
        sa1[row][o] = fmaxf(s, 0.f);
    }
    __syncthreads();

    // weights = a1 @ W2 + b2 ; senet = flat*weights + flat ; accumulate stats
    float v[4][8];
    float lsum[4] = {0.f, 0.f, 0.f, 0.f};
    float lsq[4]  = {0.f, 0.f, 0.f, 0.f};
    #pragma unroll
    for (int r8 = 0; r8 < 8; r8++) {
        int e = tid + r8 * 256;
        float bb = b2[e];
        float w0 = bb, w1 = bb, w2a = bb, w3 = bb;
        #pragma unroll 8
        for (int j = 0; j < RED_; j++) {
            float w2e = W2[j * EMB_ + e];
            w0  = fmaf(sa1[0][j], w2e, w0);
            w1  = fmaf(sa1[1][j], w2e, w1);
            w2a = fmaf(sa1[2][j], w2e, w2a);
            w3  = fmaf(sa1[3][j], w2e, w3);
        }
        float f0 = sx[0][e], f1 = sx[1][e], f2 = sx[2][e], f3 = sx[3][e];
        float s0 = fmaf(f0, w0, f0);
        float s1 = fmaf(f1, w1, f1);
        float s2 = fmaf(f2, w2a, f2);
        float s3 = fmaf(f3, w3, f3);
        v[0][r8] = s0; v[1][r8] = s1; v[2][r8] = s2; v[3][r8] = s3;
        lsum[0] += s0; lsq[0] += s0 * s0;
        lsum[1] += s1; lsq[1] += s1 * s1;
        lsum[2] += s2; lsq[2] += s2 * s2;
        lsum[3] += s3; lsq[3] += s3 * s3;
    }
    // block reduce (4 rows)
    #pragma unroll
    for (int o = 16; o; o >>= 1) {
        #pragma unroll
        for (int r = 0; r < 4; r++) {
            lsum[r] += __shfl_down_sync(0xFFFFFFFFu, lsum[r], o);
            lsq[r]  += __shfl_down_sync(0xFFFFFFFFu, lsq[r], o);
        }
    }
    if ((tid & 31) == 0) {
        int w = tid >> 5;
        #pragma unroll
        for (int r = 0; r < 4; r++) { rsum[r][w] = lsum[r]; rsq[r][w] = lsq[r]; }
    }
    __syncthreads();
    if (tid < 4) {
        float a = 0.f, c = 0.f;
        #pragma unroll
        for (int i = 0; i < 8; i++) { a += rsum[tid][i]; c += rsq[tid][i]; }
        float mu = a * (1.0f / EMB_);
        float var = c * (1.0f / EMB_) - mu * mu;
        s_mu[tid] = mu;
        s_rstd[tid] = rsqrtf(var + EPS_);
    }
    __syncthreads();
    #pragma unroll
    for (int r = 0; r < 4; r++) {
        float mu = s_mu[r], rstd = s_rstd[r];
        float* ob = out + (size_t)(b0 + r) * ROWSTRIDE_;
        #pragma unroll
        for (int r8 = 0; r8 < 8; r8++) {
            int e = tid + r8 * 256;
            ob[e] = fmaf((v[r][r8] - mu) * rstd, ln_scale[e], ln_bias[e]);
        }
    }
}

// ---------------------------------------------------------------------------
// Kernel 2: dots[b,p] = x_i^T Wp[p] x_j + bp[p].x_j
// grid (P, B/128); block 256 threads = 16x16; each thread 8 rows x 4 cols.
// FFMA2 (f32x2) column-pairing: per warp-d 16 FFMA2 (32 fma-pipe cyc) vs 64
// for scalar FFMA. w-pairs contiguous (LDS.64), xi duplicated via 1 MOV.
// ---------------------------------------------------------------------------
__global__ __launch_bounds__(256) void bilinear_dots_kernel(
    const float* __restrict__ x, const float* __restrict__ Wp,
    const float* __restrict__ bp)
{
    __shared__ float sW[64 * 64];        // Wp[p], [d][e]   (16 KB)
    __shared__ float sXi[128 * 64];      // 128 batches x 64 d (32 KB)

    int p = blockIdx.x;
    int b0 = blockIdx.y * 128;
    int tid = threadIdx.x;

    // pair (i, j) from p
    int i = 0, rem = p, cnt = F_ - 1;
    while (rem >= cnt) { rem -= cnt; i++; cnt--; }
    int j = i + 1 + rem;

    // load Wp[p]: 4096 floats = 1024 float4
    const float4* Wp4 = (const float4*)(Wp + (size_t)p * 4096);
    #pragma unroll
    for (int r = 0; r < 4; r++)
        ((float4*)sW)[tid + r * 256] = Wp4[tid + r * 256];

    // load Xi tile (128 rows x 64 floats)
    #pragma unroll
    for (int r = 0; r < 8; r++) {
        int idx = tid + r * 256;
        int row = idx >> 4, cg = idx & 15;
        *(float4*)(sXi + row * 64 + cg * 4) =
            *(const float4*)(x + (size_t)(b0 + row) * EMB_ + i * D_ + cg * 4);
    }
    __syncthreads();

    int tx = tid & 15, ty = tid >> 4;
    int colBase = tx * 4;
    int rowBase = ty * 8;

    unsigned long long accp[8][2];   // [row][column-pair]
    #pragma unroll
    for (int r = 0; r < 8; r++) {
        accp[r][0] = pack2(0.f, 0.f);
        accp[r][1] = pack2(0.f, 0.f);
    }

    #pragma unroll 4
    for (int d = 0; d < 64; d++) {
        const unsigned long long* wp =
            (const unsigned long long*)&sW[d * 64 + colBase];
        unsigned long long w01 = wp[0];   // {w[c0], w[c1]}
        unsigned long long w23 = wp[1];   // {w[c2], w[c3]}
        #pragma unroll
        for (int rr = 0; rr < 8; rr++) {
            float xi = sXi[(rowBase + rr) * 64 + d];
            unsigned long long xid = pack2(xi, xi);
            fma2(accp[rr][0], xid, w01);
            fma2(accp[rr][1], xid, w23);
        }
    }

    float4 bpv = *(const float4*)(bp + (size_t)p * D_ + colBase);
    float part[8];
    #pragma unroll
    for (int rr = 0; rr < 8; rr++) {
        int row = rowBase + rr;
        float4 xj = *(const float4*)(x + (size_t)(b0 + row) * EMB_ + j * D_ + colBase);
        float2 a01 = unpack2(accp[rr][0]);
        float2 a23 = unpack2(accp[rr][1]);
        part[rr] = (a01.x + bpv.x) * xj.x + (a01.y + bpv.y) * xj.y
                 + (a23.x + bpv.z) * xj.z + (a23.y + bpv.w) * xj.w;
    }
    // reduce over the 16 tx lanes (each half-warp is one ty group)
    #pragma unroll
    for (int o = 8; o; o >>= 1) {
        #pragma unroll
        for (int rr = 0; rr < 8; rr++)
            part[rr] += __shfl_down_sync(0xFFFFFFFFu, part[rr], o, 16);
    }
    if (tx == 0) {
        #pragma unroll
        for (int rr = 0; rr < 8; rr++)
            g_dots[(size_t)(b0 + rowBase + rr) * P_ + p] = part[rr];
    }
}

// ---------------------------------------------------------------------------
// Kernel 3: bilinear = dots (1024x496) @ Wo (496x512) + bo -> out[:, 2048:]
// BM=BN=64, BK=16, 256 threads, 4x4 micro-tile, FFMA2 column-paired
// ---------------------------------------------------------------------------
__global__ __launch_bounds__(256) void bilinear_out_kernel(
    const float* __restrict__ Wo, const float* __restrict__ bo,
    float* __restrict__ out)
{
    __shared__ float sA[16][68];   // [k][m]
    __shared__ float sB[16][64];   // [k][n]

    int m0 = blockIdx.x * 64;
    int n0 = blockIdx.y * 64;
    int tid = threadIdx.x;
    int tx = tid & 15, ty = tid >> 4;

    unsigned long long accp[4][2];
    #pragma unroll
    for (int r = 0; r < 4; r++) {
        accp[r][0] = pack2(0.f, 0.f);
        accp[r][1] = pack2(0.f, 0.f);
    }

    for (int kc = 0; kc < P_; kc += 16) {
        // A tile (dots): thread loads float4 along k, stores transposed
        {
            int row = tid >> 2, kq = tid & 3;
            float4 a = *(const float4*)(&g_dots[(size_t)(m0 + row) * P_ + kc + kq * 4]);
            sA[kq * 4 + 0][row] = a.x;
            sA[kq * 4 + 1][row] = a.y;
            sA[kq * 4 + 2][row] = a.z;
            sA[kq * 4 + 3][row] = a.w;
        }
        // B tile (Wo)
        {
            int kk = tid >> 4, cg = tid & 15;
            float4 bvec = *(const float4*)(Wo + (size_t)(kc + kk) * OUT_ + n0 + cg * 4);
            *(float4*)&sB[kk][cg * 4] = bvec;
        }
        __syncthreads();

        #pragma unroll
        for (int kk = 0; kk < 16; kk++) {
            const unsigned long long* bvp =
                (const unsigned long long*)&sB[kk][tx * 4];
            unsigned long long b01 = bvp[0];
            unsigned long long b23 = bvp[1];
            #pragma unroll
            for (int rr = 0; rr < 4; rr++) {
                float a = sA[kk][ty * 4 + rr];
                unsigned long long ad = pack2(a, a);
                fma2(accp[rr][0], ad, b01);
                fma2(accp[rr][1], ad, b23);
            }
        }
        __syncthreads();
    }

    #pragma unroll
    for (int rr = 0; rr < 4; rr++) {
        int row = m0 + ty * 4 + rr;
        float* orow = out + (size_t)row * ROWSTRIDE_ + EMB_ + n0 + tx * 4;
        float4 bov = *(const float4*)(bo + n0 + tx * 4);
        float2 a01 = unpack2(accp[rr][0]);
        float2 a23 = unpack2(accp[rr][1]);
        float4 o;
        o.x = a01.x + bov.x;
        o.y = a01.y + bov.y;
        o.z = a23.x + bov.z;
        o.w = a23.y + bov.w;
        *(float4*)orow = o;
    }
}

// ---------------------------------------------------------------------------
extern "C" void kernel_launch(void* const* d_in, const int* in_sizes, int n_in,
                              void* d_out, int out_size)
{
    const float* x        = (const float*)d_in[0];
    const float* W1       = (const float*)d_in[1];
    const float* b1       = (const float*)d_in[2];
    const float* W2       = (const float*)d_in[3];
    const float* b2       = (const float*)d_in[4];
    const float* ln_scale = (const float*)d_in[5];
    const float* ln_bias  = (const float*)d_in[6];
    const float* Wp       = (const float*)d_in[7];
    const float* bp       = (const float*)d_in[8];
    const float* Wo       = (const float*)d_in[9];
    const float* bo       = (const float*)d_in[10];
    float* out = (float*)d_out;

    bilinear_dots_kernel<<<dim3(P_, B_ / 128), 256>>>(x, Wp, bp);
    senet_kernel<<<B_ / 4, 256>>>(x, W1, b1, W2, b2, ln_scale, ln_bias, out);
    bilinear_out_kernel<<<dim3(B_ / 64, OUT_ / 64), 256>>>(Wo, bo, out);
}